// round 12
// baseline (speedup 1.0000x reference)
#include <cuda_runtime.h>
#include <math.h>
#include <stdint.h>

#define VOCAB 32000
#define EMB 256
#define HID 256
#define BATCH 64
#define SEQT 2048

// Scratch: V[v][j] = sum_e emb[v][e]*W_ih[e][j] + b_ih[j] + b_hh[j]  (32 MB, L2-resident)
__device__ float g_V[VOCAB * HID];

// ---------------------------------------------------------------------------
// f32x2 packed helpers (PTX-only; ptxas won't auto-fuse)
// ---------------------------------------------------------------------------
__device__ __forceinline__ unsigned long long pack2(float lo, float hi) {
    unsigned long long r;
    asm("mov.b64 %0, {%1, %2};" : "=l"(r) : "f"(lo), "f"(hi));
    return r;
}
__device__ __forceinline__ void fma2(unsigned long long& acc,
                                     unsigned long long a, unsigned long long b) {
    asm("fma.rn.f32x2 %0, %1, %2, %0;" : "+l"(acc) : "l"(a), "l"(b));
}
__device__ __forceinline__ unsigned long long add2(unsigned long long a,
                                                   unsigned long long b) {
    unsigned long long r;
    asm("add.rn.f32x2 %0, %1, %2;" : "=l"(r) : "l"(a), "l"(b));
    return r;
}
__device__ __forceinline__ void unpack2(unsigned long long v, float& lo, float& hi) {
    asm("mov.b64 {%0, %1}, %2;" : "=f"(lo), "=f"(hi) : "l"(v));
}

// Cluster helpers
__device__ __forceinline__ uint32_t smem_u32(const void* p) {
    uint32_t a;
    asm("{ .reg .u64 t; cvta.to.shared.u64 t, %1; cvt.u32.u64 %0, t; }"
        : "=r"(a) : "l"(p));
    return a;
}
__device__ __forceinline__ uint32_t mapa_peer(uint32_t addr, uint32_t rank) {
    uint32_t r;
    asm("mapa.shared::cluster.u32 %0, %1, %2;" : "=r"(r) : "r"(addr), "r"(rank));
    return r;
}
// Weak remote data store
__device__ __forceinline__ void st_cluster_f32(uint32_t addr, float v) {
    asm volatile("st.shared::cluster.f32 [%0], %1;" :: "r"(addr), "f"(v) : "memory");
}
// Release flag store: orders THIS thread's prior remote data store before it
__device__ __forceinline__ void st_cluster_release_u32(uint32_t addr, uint32_t v) {
    asm volatile("st.release.cluster.shared::cluster.u32 [%0], %1;"
                 :: "r"(addr), "r"(v) : "memory");
}
// Acquire flag load (local SMEM slot, written by cluster peer)
__device__ __forceinline__ uint32_t lds_acquire_u32(uint32_t addr) {
    uint32_t v;
    asm volatile("ld.acquire.cluster.shared::cta.u32 %0, [%1];"
                 : "=r"(v) : "r"(addr) : "memory");
    return v;
}
#define CLUSTER_SYNC() do { \
    asm volatile("barrier.cluster.arrive.aligned;" ::: "memory"); \
    asm volatile("barrier.cluster.wait.aligned;" ::: "memory"); \
} while (0)

// ---------------------------------------------------------------------------
// Kernel 1: vocab projection GEMM  [32000,256] x [256,256] + bias  (f32x2)
// ---------------------------------------------------------------------------
__global__ void __launch_bounds__(256) vocab_proj_kernel(
    const float* __restrict__ emb, const float* __restrict__ W_ih,
    const float* __restrict__ b_ih, const float* __restrict__ b_hh)
{
    __shared__ float As_T[32][68];
    const int row0 = blockIdx.x * 64;
    const int j = threadIdx.x;

    const float bias = b_ih[j] + b_hh[j];

    unsigned long long acc[32];
#pragma unroll
    for (int p = 0; p < 32; p++) acc[p] = 0ull;

#pragma unroll 1
    for (int k0 = 0; k0 < EMB; k0 += 32) {
        __syncthreads();
#pragma unroll
        for (int it = 0; it < 8; it++) {
            int idx = it * 256 + threadIdx.x;
            int r  = idx >> 5;
            int kk = idx & 31;
            As_T[kk][r] = emb[(size_t)(row0 + r) * EMB + (k0 + kk)];
        }
        __syncthreads();

        float wt[32];
#pragma unroll
        for (int kk = 0; kk < 32; kk++)
            wt[kk] = W_ih[(size_t)(k0 + kk) * HID + j];

#pragma unroll
        for (int kk = 0; kk < 32; kk++) {
            unsigned long long ws = pack2(wt[kk], wt[kk]);
#pragma unroll
            for (int rp2 = 0; rp2 < 16; rp2++) {
                ulonglong2 av = *(const ulonglong2*)&As_T[kk][4 * rp2];
                fma2(acc[2 * rp2 + 0], av.x, ws);
                fma2(acc[2 * rp2 + 1], av.y, ws);
            }
        }
    }

#pragma unroll
    for (int p = 0; p < 32; p++) {
        float lo, hi;
        unpack2(acc[p], lo, hi);
        g_V[(size_t)(row0 + 2 * p + 0) * HID + j] = lo + bias;
        g_V[(size_t)(row0 + 2 * p + 1) * HID + j] = hi + bias;
    }
}

// ---------------------------------------------------------------------------
// Kernel 2: recurrence. 2-CTA cluster per chain (128 CTAs), flag handshake.
// Thread t: col = t&127, kh = t>>7.
//   grpL (kh == rank):  FMA over locally-produced h half -> partial[col].
//   grpR (kh != rank):  poll per-column step flags (ld.acquire), FMA over
//                       incoming peer h half, merge, tanh, store h local +
//                       weak st to peer h + release-store flag = step+1.
// Flags carry the step index (parity-split buffers) -> no re-arm, no mbar.
// ---------------------------------------------------------------------------
__global__ void __launch_bounds__(256, 1) __cluster_dims__(2, 1, 1)
rnn_kernel(const int* __restrict__ source, const float* __restrict__ W_hh,
           float* __restrict__ out)
{
    __shared__ float hs[2][256];
    __shared__ float partial[128];
    __shared__ int   srcs[SEQT];
    __shared__ __align__(16) unsigned int flags[2][128];

    const int t   = threadIdx.x;
    const int col = t & 127;
    const int kh  = t >> 7;
    const int l   = t & 31;
    const int k0  = kh * 128;
    const int b   = blockIdx.x >> 1;

    uint32_t rank;
    asm("mov.u32 %0, %%cluster_ctarank;" : "=r"(rank));

    const bool is_fin = (kh != (int)rank);          // grpR: consumers+finalizers
    const int  jout   = (int)rank * 128 + col;      // this CTA's output column

    for (int i = t; i < SEQT; i += 256) srcs[i] = source[b * SEQT + i];

    // W_hh[k0..k0+127][jout] register-resident as 64 f32x2
    unsigned long long wreg[64];
#pragma unroll
    for (int i = 0; i < 64; i++)
        wreg[i] = pack2(W_hh[(size_t)(k0 + 2 * i + 0) * HID + jout],
                        W_hh[(size_t)(k0 + 2 * i + 1) * HID + jout]);

    hs[0][t] = 0.0f;
    hs[1][t] = 0.0f;
    if (t < 128) { flags[0][t] = 0u; flags[1][t] = 0u; }

    // Finalizer remote targets: peer hs slot + peer flag slot, both buffers.
    uint32_t peer_h[2], peer_f[2];
#pragma unroll
    for (int q = 0; q < 2; q++) {
        peer_h[q] = mapa_peer(smem_u32(&hs[q][jout]), rank ^ 1u);
        peer_f[q] = mapa_peer(smem_u32(&flags[q][col]), rank ^ 1u);
    }
    // Consumer poll base: 4 flags per lane (16B)
    const uint32_t fpoll[2] = { smem_u32(&flags[0][0]) + 16u * (uint32_t)l,
                                smem_u32(&flags[1][0]) + 16u * (uint32_t)l };

    __syncthreads();
    CLUSTER_SYNC();  // zeroed hs + flags visible cluster-wide

    float hval = 0.0f;

#pragma unroll 1
    for (int step = 0; step < SEQT; step++) {
        const int cur = step & 1;
        const int nxt = cur ^ 1;

        float xv = 0.0f;
        if (is_fin) {
            // Prefetch x-projection (L2 gather; consumed at the tail)
            xv = g_V[(size_t)srcs[step] * HID + jout];

            // Poll the 128 per-column flags for this buffer == step.
            // (step 0: flags are 0 -> passes immediately.)
            const uint32_t tgt = (uint32_t)step;
            const uint32_t fa  = fpoll[cur];
            bool ok;
            do {
                uint32_t f0 = lds_acquire_u32(fa);
                uint32_t f1 = lds_acquire_u32(fa + 4);
                uint32_t f2 = lds_acquire_u32(fa + 8);
                uint32_t f3 = lds_acquire_u32(fa + 12);
                ok = (f0 == tgt) & (f1 == tgt) & (f2 == tgt) & (f3 == tgt);
            } while (!__all_sync(0xffffffffu, ok));
        }

        // FMA over this group's k-half (grpL: local h, grpR: incoming h)
        const float* hp = &hs[cur][k0];
        unsigned long long a0 = 0, a1 = 0, a2 = 0, a3 = 0;
        unsigned long long b0 = 0, b1 = 0, b2 = 0, b3 = 0;
#pragma unroll
        for (int q = 0; q < 32; q += 4) {
            ulonglong2 h0 = *(const ulonglong2*)(hp + 4 * (q + 0));
            ulonglong2 h1 = *(const ulonglong2*)(hp + 4 * (q + 1));
            ulonglong2 h2 = *(const ulonglong2*)(hp + 4 * (q + 2));
            ulonglong2 h3 = *(const ulonglong2*)(hp + 4 * (q + 3));
            fma2(a0, h0.x, wreg[2 * q + 0]); fma2(b0, h0.y, wreg[2 * q + 1]);
            fma2(a1, h1.x, wreg[2 * q + 2]); fma2(b1, h1.y, wreg[2 * q + 3]);
            fma2(a2, h2.x, wreg[2 * q + 4]); fma2(b2, h2.y, wreg[2 * q + 5]);
            fma2(a3, h3.x, wreg[2 * q + 6]); fma2(b3, h3.y, wreg[2 * q + 7]);
        }
        unsigned long long s = add2(add2(add2(a0, a1), add2(a2, a3)),
                                    add2(add2(b0, b1), add2(b2, b3)));
        float lo, hi;
        unpack2(s, lo, hi);
        const float pr = lo + hi;

        if (!is_fin) partial[col] = pr;
        __syncthreads();  // bar#1: local partials published

        if (is_fin) {
            const float pre = xv + pr + partial[col];
            const float e = __expf(2.0f * pre);
            hval = 1.0f - __fdividef(2.0f, e + 1.0f);

            hs[nxt][jout] = hval;                 // local copy (for grpL)
            st_cluster_f32(peer_h[nxt], hval);    // weak remote data store
            st_cluster_release_u32(peer_f[nxt], (uint32_t)(step + 1));  // signal
        }
        __syncthreads();  // bar#2: local h visible; recycles partial[]
    }

    if (is_fin) out[b * HID + jout] = hval;

    CLUSTER_SYNC();  // keep peer SMEM alive for in-flight final stores
}

// ---------------------------------------------------------------------------
extern "C" void kernel_launch(void* const* d_in, const int* in_sizes, int n_in,
                              void* d_out, int out_size)
{
    const int*   source    = (const int*)d_in[0];
    const float* embedding = (const float*)d_in[1];
    const float* W_ih      = (const float*)d_in[2];
    const float* W_hh      = (const float*)d_in[3];
    const float* b_ih      = (const float*)d_in[4];
    const float* b_hh      = (const float*)d_in[5];
    float* out = (float*)d_out;

    vocab_proj_kernel<<<VOCAB / 64, 256>>>(embedding, W_ih, b_ih, b_hh);
    rnn_kernel<<<BATCH * 2, 256>>>(source, W_hh, out);
}

// round 13
// speedup vs baseline: 1.7310x; 1.7310x over previous
#include <cuda_runtime.h>
#include <math.h>
#include <stdint.h>

#define VOCAB 32000
#define EMB 256
#define HID 256
#define BATCH 64
#define SEQT 2048

// Scratch: V[v][j] = sum_e emb[v][e]*W_ih[e][j] + b_ih[j] + b_hh[j]  (32 MB, L2-resident)
__device__ float g_V[VOCAB * HID];

// ---------------------------------------------------------------------------
// f32x2 packed helpers (PTX-only; ptxas won't auto-fuse)
// ---------------------------------------------------------------------------
__device__ __forceinline__ unsigned long long pack2(float lo, float hi) {
    unsigned long long r;
    asm("mov.b64 %0, {%1, %2};" : "=l"(r) : "f"(lo), "f"(hi));
    return r;
}
__device__ __forceinline__ void fma2(unsigned long long& acc,
                                     unsigned long long a, unsigned long long b) {
    asm("fma.rn.f32x2 %0, %1, %2, %0;" : "+l"(acc) : "l"(a), "l"(b));
}
__device__ __forceinline__ unsigned long long add2(unsigned long long a,
                                                   unsigned long long b) {
    unsigned long long r;
    asm("add.rn.f32x2 %0, %1, %2;" : "=l"(r) : "l"(a), "l"(b));
    return r;
}
__device__ __forceinline__ void unpack2(unsigned long long v, float& lo, float& hi) {
    asm("mov.b64 {%0, %1}, %2;" : "=f"(lo), "=f"(hi) : "l"(v));
}

// Cluster / mbarrier helpers
__device__ __forceinline__ uint32_t smem_u32(const void* p) {
    uint32_t a;
    asm("{ .reg .u64 t; cvta.to.shared.u64 t, %1; cvt.u32.u64 %0, t; }"
        : "=r"(a) : "l"(p));
    return a;
}
__device__ __forceinline__ uint32_t mapa_peer(uint32_t addr, uint32_t rank) {
    uint32_t r;
    asm("mapa.shared::cluster.u32 %0, %1, %2;" : "=r"(r) : "r"(addr), "r"(rank));
    return r;
}
__device__ __forceinline__ void mbar_init(uint32_t addr, uint32_t count) {
    asm volatile("mbarrier.init.shared.b64 [%0], %1;" :: "r"(addr), "r"(count) : "memory");
}
__device__ __forceinline__ void mbar_expect_tx(uint32_t addr, uint32_t bytes) {
    asm volatile("mbarrier.arrive.expect_tx.shared.b64 _, [%0], %1;"
                 :: "r"(addr), "r"(bytes) : "memory");
}
// ONE bulk SMEM->peer-SMEM copy; single tx completion on the peer's mbar.
__device__ __forceinline__ void bulk_copy_to_peer(uint32_t dst_cluster,
                                                  uint32_t src_cta,
                                                  uint32_t bytes,
                                                  uint32_t peer_mbar) {
    asm volatile(
        "cp.async.bulk.shared::cluster.shared::cta.mbarrier::complete_tx::bytes "
        "[%0], [%1], %2, [%3];"
        :: "r"(dst_cluster), "r"(src_cta), "r"(bytes), "r"(peer_mbar) : "memory");
}
__device__ __forceinline__ void fence_proxy_async_cta() {
    asm volatile("fence.proxy.async.shared::cta;" ::: "memory");
}
__device__ __forceinline__ void mbar_wait_parity(uint32_t addr, uint32_t parity) {
    uint32_t done;
    asm volatile(
        "{\n\t"
        ".reg .pred p;\n\t"
        "mbarrier.try_wait.parity.acquire.cluster.shared::cta.b64 p, [%1], %2;\n\t"
        "selp.b32 %0, 1, 0, p;\n\t"
        "}" : "=r"(done) : "r"(addr), "r"(parity) : "memory");
    if (!done) {
        asm volatile(
            "{\n\t"
            ".reg .pred P1;\n\t"
            "WL_%=:\n\t"
            "mbarrier.try_wait.parity.acquire.cluster.shared::cta.b64 P1, [%0], %1, 0x989680;\n\t"
            "@P1 bra.uni WD_%=;\n\t"
            "bra.uni WL_%=;\n\t"
            "WD_%=:\n\t"
            "}" :: "r"(addr), "r"(parity) : "memory");
    }
}
#define CLUSTER_SYNC() do { \
    asm volatile("barrier.cluster.arrive.aligned;" ::: "memory"); \
    asm volatile("barrier.cluster.wait.aligned;" ::: "memory"); \
} while (0)

// ---------------------------------------------------------------------------
// Kernel 1: vocab projection GEMM  [32000,256] x [256,256] + bias  (f32x2)
// ---------------------------------------------------------------------------
__global__ void __launch_bounds__(256) vocab_proj_kernel(
    const float* __restrict__ emb, const float* __restrict__ W_ih,
    const float* __restrict__ b_ih, const float* __restrict__ b_hh)
{
    __shared__ float As_T[32][68];
    const int row0 = blockIdx.x * 64;
    const int j = threadIdx.x;

    const float bias = b_ih[j] + b_hh[j];

    unsigned long long acc[32];
#pragma unroll
    for (int p = 0; p < 32; p++) acc[p] = 0ull;

#pragma unroll 1
    for (int k0 = 0; k0 < EMB; k0 += 32) {
        __syncthreads();
#pragma unroll
        for (int it = 0; it < 8; it++) {
            int idx = it * 256 + threadIdx.x;
            int r  = idx >> 5;
            int kk = idx & 31;
            As_T[kk][r] = emb[(size_t)(row0 + r) * EMB + (k0 + kk)];
        }
        __syncthreads();

        float wt[32];
#pragma unroll
        for (int kk = 0; kk < 32; kk++)
            wt[kk] = W_ih[(size_t)(k0 + kk) * HID + j];

#pragma unroll
        for (int kk = 0; kk < 32; kk++) {
            unsigned long long ws = pack2(wt[kk], wt[kk]);
#pragma unroll
            for (int rp2 = 0; rp2 < 16; rp2++) {
                ulonglong2 av = *(const ulonglong2*)&As_T[kk][4 * rp2];
                fma2(acc[2 * rp2 + 0], av.x, ws);
                fma2(acc[2 * rp2 + 1], av.y, ws);
            }
        }
    }

#pragma unroll
    for (int p = 0; p < 32; p++) {
        float lo, hi;
        unpack2(acc[p], lo, hi);
        g_V[(size_t)(row0 + 2 * p + 0) * HID + j] = lo + bias;
        g_V[(size_t)(row0 + 2 * p + 1) * HID + j] = hi + bias;
    }
}

// ---------------------------------------------------------------------------
// Kernel 2: recurrence. 2-CTA cluster per chain, BULK h exchange (R4 skeleton).
// Warp w: pair p = w&3 (cols p*32..p*32+31, one col/lane), kh = w>>2.
//  local warp  (kh == rank):   FMA over own-produced h half -> partial[col]
//  remote warp (kh == rank^1): wait mbar (ONE 512B tx), FMA over peer h half,
//     pair-bar merge, tanh, STS h local; then one elected thread bulk-copies
//     the whole 512B h half to the peer with a single complete_tx.
// ---------------------------------------------------------------------------
__global__ void __launch_bounds__(256, 1) __cluster_dims__(2, 1, 1)
rnn_kernel(const int* __restrict__ source, const float* __restrict__ W_hh,
           float* __restrict__ out)
{
    __shared__ __align__(16) float hs[2][256];
    __shared__ float partial[128];
    __shared__ int   srcs[SEQT];
    __shared__ __align__(8) unsigned long long mbar[2];

    const int t  = threadIdx.x;
    const int w  = t >> 5;
    const int l  = t & 31;
    const int p  = w & 3;         // pair id
    const int kh = w >> 2;        // k-half this warp multiplies
    const int col = p * 32 + l;   // local output column 0..127
    const int k0  = kh * 128;
    const int b   = blockIdx.x >> 1;

    uint32_t rank;
    asm("mov.u32 %0, %%cluster_ctarank;" : "=r"(rank));

    const int  jout      = (int)rank * 128 + col;   // global output column
    const bool is_remote = (kh != (int)rank);       // warp-uniform

    for (int i = t; i < SEQT; i += 256) srcs[i] = source[b * SEQT + i];

    // W_hh[k0..k0+127][jout] register-resident as 64 f32x2
    unsigned long long wreg[64];
#pragma unroll
    for (int i = 0; i < 64; i++)
        wreg[i] = pack2(W_hh[(size_t)(k0 + 2 * i + 0) * HID + jout],
                        W_hh[(size_t)(k0 + 2 * i + 1) * HID + jout]);

    hs[0][t] = 0.0f;
    hs[1][t] = 0.0f;
    if (t == 0) {
        mbar_init(smem_u32(&mbar[0]), 1);
        mbar_init(smem_u32(&mbar[1]), 1);
        mbar_expect_tx(smem_u32(&mbar[0]), 512);  // pre-arm phase 0 of both
        mbar_expect_tx(smem_u32(&mbar[1]), 512);
    }

    // Bulk-copy endpoints: our produced half [rank*128, rank*128+128)
    const uint32_t src_half[2] = { smem_u32(&hs[0][(int)rank * 128]),
                                   smem_u32(&hs[1][(int)rank * 128]) };
    uint32_t dst_half[2], peer_mbar[2], mbar_local[2];
#pragma unroll
    for (int q = 0; q < 2; q++) {
        dst_half[q]  = mapa_peer(src_half[q], rank ^ 1u);
        peer_mbar[q] = mapa_peer(smem_u32(&mbar[q]), rank ^ 1u);
        mbar_local[q] = smem_u32(&mbar[q]);
    }

    __syncthreads();
    CLUSTER_SYNC();  // mbar init + expect_tx visible cluster-wide

    float hval = 0.0f;

#pragma unroll 1
    for (int step = 0; step < SEQT; step++) {
        const int cur = step & 1;
        const int nxt = cur ^ 1;

        if (is_remote) {
            // Prefetch x-projection (L2 gather) — hides under wait+FMA
            float xv = g_V[(size_t)srcs[step] * HID + jout];

            if (step > 0) {
                mbar_wait_parity(mbar_local[cur], ((uint32_t)(step - 1) >> 1) & 1u);
                // Re-arm this mbar's next phase (filled 2 steps from now)
                if (p == 0 && l == 0) mbar_expect_tx(mbar_local[cur], 512);
            }

            const float* hp = &hs[cur][k0];
            unsigned long long a0 = 0, a1 = 0, a2 = 0, a3 = 0;
            unsigned long long b0 = 0, b1 = 0, b2 = 0, b3 = 0;
#pragma unroll
            for (int q = 0; q < 32; q += 4) {
                ulonglong2 h0 = *(const ulonglong2*)(hp + 4 * (q + 0));
                ulonglong2 h1 = *(const ulonglong2*)(hp + 4 * (q + 1));
                ulonglong2 h2 = *(const ulonglong2*)(hp + 4 * (q + 2));
                ulonglong2 h3 = *(const ulonglong2*)(hp + 4 * (q + 3));
                fma2(a0, h0.x, wreg[2 * q + 0]); fma2(b0, h0.y, wreg[2 * q + 1]);
                fma2(a1, h1.x, wreg[2 * q + 2]); fma2(b1, h1.y, wreg[2 * q + 3]);
                fma2(a2, h2.x, wreg[2 * q + 4]); fma2(b2, h2.y, wreg[2 * q + 5]);
                fma2(a3, h3.x, wreg[2 * q + 6]); fma2(b3, h3.y, wreg[2 * q + 7]);
            }
            unsigned long long s = add2(add2(add2(a0, a1), add2(a2, a3)),
                                        add2(add2(b0, b1), add2(b2, b3)));
            float lo, hi;
            unpack2(s, lo, hi);
            float pr = lo + hi;

            asm volatile("bar.sync %0, 64;" :: "r"(p + 1) : "memory");  // pair merge

            float pre = xv + pr + partial[col];
            float e = __expf(2.0f * pre);
            hval = 1.0f - __fdividef(2.0f, e + 1.0f);

            hs[nxt][jout] = hval;   // local copy (also the bulk-copy source)

            // Gather-complete barrier among the 4 finalizer warps, then ONE
            // bulk copy: 512B, single transit, single tx completion.
            asm volatile("bar.sync 5, 128;" ::: "memory");
            if (p == 0 && l == 0) {
                fence_proxy_async_cta();  // order STS before async-proxy read
                bulk_copy_to_peer(dst_half[nxt], src_half[nxt], 512u,
                                  peer_mbar[nxt]);
            }
        } else {
            const float* hp = &hs[cur][k0];
            unsigned long long a0 = 0, a1 = 0, a2 = 0, a3 = 0;
            unsigned long long b0 = 0, b1 = 0, b2 = 0, b3 = 0;
#pragma unroll
            for (int q = 0; q < 32; q += 4) {
                ulonglong2 h0 = *(const ulonglong2*)(hp + 4 * (q + 0));
                ulonglong2 h1 = *(const ulonglong2*)(hp + 4 * (q + 1));
                ulonglong2 h2 = *(const ulonglong2*)(hp + 4 * (q + 2));
                ulonglong2 h3 = *(const ulonglong2*)(hp + 4 * (q + 3));
                fma2(a0, h0.x, wreg[2 * q + 0]); fma2(b0, h0.y, wreg[2 * q + 1]);
                fma2(a1, h1.x, wreg[2 * q + 2]); fma2(b1, h1.y, wreg[2 * q + 3]);
                fma2(a2, h2.x, wreg[2 * q + 4]); fma2(b2, h2.y, wreg[2 * q + 5]);
                fma2(a3, h3.x, wreg[2 * q + 6]); fma2(b3, h3.y, wreg[2 * q + 7]);
            }
            unsigned long long s = add2(add2(add2(a0, a1), add2(a2, a3)),
                                        add2(add2(b0, b1), add2(b2, b3)));
            float lo, hi;
            unpack2(s, lo, hi);
            partial[col] = lo + hi;

            asm volatile("bar.sync %0, 64;" :: "r"(p + 1) : "memory");  // pair merge
        }

        __syncthreads();  // local h visible to local warps; recycles partial[]
    }

    if (is_remote) out[b * HID + jout] = hval;

    CLUSTER_SYNC();  // keep peer SMEM alive for in-flight final bulk copies
}

// ---------------------------------------------------------------------------
extern "C" void kernel_launch(void* const* d_in, const int* in_sizes, int n_in,
                              void* d_out, int out_size)
{
    const int*   source    = (const int*)d_in[0];
    const float* embedding = (const float*)d_in[1];
    const float* W_ih      = (const float*)d_in[2];
    const float* W_hh      = (const float*)d_in[3];
    const float* b_ih      = (const float*)d_in[4];
    const float* b_hh      = (const float*)d_in[5];
    float* out = (float*)d_out;

    vocab_proj_kernel<<<VOCAB / 64, 256>>>(embedding, W_ih, b_ih, b_hh);
    rnn_kernel<<<BATCH * 2, 256>>>(source, W_hh, out);
}